// round 1
// baseline (speedup 1.0000x reference)
#include <cuda_runtime.h>
#include <cuda_bf16.h>
#include <math.h>

#define BATCH 16384
#define FF    39
#define DD    16
#define DHD   32
#define VOCAB 10000
#define WARPS 8

// per-warp shared region layout (floats)
//  e:    39*32 = 1248   @0
//  kT:   32*41 = 1312   @1248
//  v:    39*32 = 1248   @2560
//  qrow: 32             @3808
//  srow: 40             @3840
//  mA:   128            @3880
//  mB:   64             @4008
#define PW    4072
#define WBUF  4096   // shared w1 chunk: 32 rows x 128 cols

struct Params {
  const int* x; const float* emb;
  const float* wq0; const float* wk0; const float* wv0; const float* wr0;
  const float* wq1; const float* wk1; const float* wv1; const float* wr1;
  const float* wq2; const float* wk2; const float* wv2; const float* wr2;
  const float* w1; const float* b1; const float* w2; const float* b2;
  const float* w3; const float* b3; const float* w4; const float* b4;
  float* out;
};

template<int DIN>
__device__ __forceinline__ void attn_layer(
    float* eB, float* kT, float* vB, float* qrow, float* srow,
    const float* __restrict__ wq, const float* __restrict__ wk,
    const float* __restrict__ wv, const float* __restrict__ wr, int lane)
{
  // ---- Phase A: K^T and V for all 39 rows (wk/wv columns in registers) ----
  float wkc[DIN], wvc[DIN];
  #pragma unroll
  for (int d = 0; d < DIN; d++) { wkc[d] = wk[d*DHD + lane]; wvc[d] = wv[d*DHD + lane]; }
  #pragma unroll 1
  for (int g = 0; g < FF; g++) {
    const float4* er4 = (const float4*)(eB + g*DHD);
    float ka = 0.f, va = 0.f;
    #pragma unroll
    for (int d4 = 0; d4 < DIN/4; d4++) {
      float4 ev = er4[d4];
      ka += ev.x*wkc[4*d4+0]; va += ev.x*wvc[4*d4+0];
      ka += ev.y*wkc[4*d4+1]; va += ev.y*wvc[4*d4+1];
      ka += ev.z*wkc[4*d4+2]; va += ev.z*wvc[4*d4+2];
      ka += ev.w*wkc[4*d4+3]; va += ev.w*wvc[4*d4+3];
    }
    kT[lane*41 + g]  = ka;   // (lane*41+g)%32 conflict-free
    vB[g*DHD + lane] = va;
  }
  // ---- Phase B: per-row q, scores, softmax, out (wq/wr columns in regs) ----
  float wqc[DIN], wrc[DIN];
  #pragma unroll
  for (int d = 0; d < DIN; d++) { wqc[d] = wq[d*DHD + lane]; wrc[d] = wr[d*DHD + lane]; }
  __syncwarp();
  const int  g2   = lane + 32;
  const bool has2 = (g2 < FF);
  const int  g2k  = has2 ? g2 : 0;
  #pragma unroll 1
  for (int f = 0; f < FF; f++) {
    const float4* er4 = (const float4*)(eB + f*DHD);
    float qa = 0.f, ra = 0.f;
    #pragma unroll
    for (int d4 = 0; d4 < DIN/4; d4++) {
      float4 ev = er4[d4];
      qa += ev.x*wqc[4*d4+0]; ra += ev.x*wrc[4*d4+0];
      qa += ev.y*wqc[4*d4+1]; ra += ev.y*wrc[4*d4+1];
      qa += ev.z*wqc[4*d4+2]; ra += ev.z*wrc[4*d4+2];
      qa += ev.w*wqc[4*d4+3]; ra += ev.w*wrc[4*d4+3];
    }
    qrow[lane] = qa;
    __syncwarp();
    // scores: lane covers g=lane and (lane<7) g=lane+32
    float s1 = 0.f, s2 = 0.f;
    #pragma unroll
    for (int c4 = 0; c4 < 8; c4++) {
      float4 qv = ((const float4*)qrow)[c4];
      int c = 4*c4;
      s1 += qv.x*kT[(c+0)*41+lane]; s2 += qv.x*kT[(c+0)*41+g2k];
      s1 += qv.y*kT[(c+1)*41+lane]; s2 += qv.y*kT[(c+1)*41+g2k];
      s1 += qv.z*kT[(c+2)*41+lane]; s2 += qv.z*kT[(c+2)*41+g2k];
      s1 += qv.w*kT[(c+3)*41+lane]; s2 += qv.w*kT[(c+3)*41+g2k];
    }
    float mx = has2 ? fmaxf(s1, s2) : s1;
    #pragma unroll
    for (int o = 16; o; o >>= 1) mx = fmaxf(mx, __shfl_xor_sync(0xffffffffu, mx, o));
    float p1 = __expf(s1 - mx);
    float p2 = has2 ? __expf(s2 - mx) : 0.f;
    float sum = p1 + p2;
    #pragma unroll
    for (int o = 16; o; o >>= 1) sum += __shfl_xor_sync(0xffffffffu, sum, o);
    float inv = 1.0f / sum;
    srow[lane] = p1 * inv;
    if (has2) srow[g2] = p2 * inv;
    __syncwarp();
    // out[f][lane] = sum_g att[f][g]*v[g][lane] + residual, then relu, in-place
    float acc = ra;
    #pragma unroll
    for (int g4 = 0; g4 < 9; g4++) {
      float4 sv = ((const float4*)srow)[g4];
      int g = 4*g4;
      acc += sv.x*vB[(g+0)*DHD+lane];
      acc += sv.y*vB[(g+1)*DHD+lane];
      acc += sv.z*vB[(g+2)*DHD+lane];
      acc += sv.w*vB[(g+3)*DHD+lane];
    }
    acc += srow[36]*vB[36*DHD+lane];
    acc += srow[37]*vB[37*DHD+lane];
    acc += srow[38]*vB[38*DHD+lane];
    eB[f*DHD + lane] = fmaxf(acc, 0.f);
    __syncwarp();
  }
}

__global__ void __launch_bounds__(256, 1) autoint_kernel(Params p)
{
  extern __shared__ float sm[];
  const int tid  = threadIdx.x;
  const int warp = tid >> 5;
  const int lane = tid & 31;
  const int samp = blockIdx.x * WARPS + warp;

  float* wbuf = sm;                        // [32][128] w1 chunk (CTA-shared)
  float* wp   = sm + WBUF + warp * PW;     // per-warp region
  float* eB   = wp;
  float* kT   = wp + 1248;
  float* vB   = wp + 2560;
  float* qrow = wp + 3808;
  float* srow = wp + 3840;
  float* mA   = wp + 3880;
  float* mB   = wp + 4008;

  // ---- embedding gather: e0[f][d] = emb[(x[f] + f*VOCAB)*16 + d] ----
  {
    const int* xr = p.x + samp * FF;
    for (int i = lane; i < FF * DD; i += 32) {
      int f = i >> 4, d = i & 15;
      int row = xr[f] + f * VOCAB;
      eB[f * DHD + d] = p.emb[row * DD + d];
    }
  }
  __syncwarp();

  attn_layer<16>(eB, kT, vB, qrow, srow, p.wq0, p.wk0, p.wv0, p.wr0, lane);
  attn_layer<32>(eB, kT, vB, qrow, srow, p.wq1, p.wk1, p.wv1, p.wr1, lane);
  attn_layer<32>(eB, kT, vB, qrow, srow, p.wq2, p.wk2, p.wv2, p.wr2, lane);

  __syncthreads();

  // ---- MLP1: h(1248) -> 128, output-stationary, 4 samples per thread ----
  const int o  = tid & 127;
  const int sg = tid >> 7;   // 0: samples 0..3, 1: samples 4..7
  const float* h0 = sm + WBUF + (sg*4 + 0) * PW;
  const float* h1 = sm + WBUF + (sg*4 + 1) * PW;
  const float* h2 = sm + WBUF + (sg*4 + 2) * PW;
  const float* h3 = sm + WBUF + (sg*4 + 3) * PW;
  float a0 = 0.f, a1 = 0.f, a2 = 0.f, a3 = 0.f;
  #pragma unroll 1
  for (int chunk = 0; chunk < 39; chunk++) {
    const int k0 = chunk * 32;
    const float4* src = (const float4*)(p.w1 + k0 * 128);
    float4* dst = (float4*)wbuf;
    #pragma unroll
    for (int i = 0; i < 4; i++) dst[tid + 256*i] = src[tid + 256*i];
    __syncthreads();
    #pragma unroll
    for (int kk = 0; kk < 32; kk += 4) {
      float4 v0 = *(const float4*)(h0 + k0 + kk);
      float4 v1 = *(const float4*)(h1 + k0 + kk);
      float4 v2 = *(const float4*)(h2 + k0 + kk);
      float4 v3 = *(const float4*)(h3 + k0 + kk);
      float w0 = wbuf[(kk+0)*128 + o];
      float w1v = wbuf[(kk+1)*128 + o];
      float w2v = wbuf[(kk+2)*128 + o];
      float w3v = wbuf[(kk+3)*128 + o];
      a0 += v0.x*w0 + v0.y*w1v + v0.z*w2v + v0.w*w3v;
      a1 += v1.x*w0 + v1.y*w1v + v1.z*w2v + v1.w*w3v;
      a2 += v2.x*w0 + v2.y*w1v + v2.z*w2v + v2.w*w3v;
      a3 += v3.x*w0 + v3.y*w1v + v3.z*w2v + v3.w*w3v;
    }
    __syncthreads();
  }
  {
    float bb = p.b1[o];
    (sm + WBUF + (sg*4 + 0)*PW + 3880)[o] = fmaxf(a0 + bb, 0.f);
    (sm + WBUF + (sg*4 + 1)*PW + 3880)[o] = fmaxf(a1 + bb, 0.f);
    (sm + WBUF + (sg*4 + 2)*PW + 3880)[o] = fmaxf(a2 + bb, 0.f);
    (sm + WBUF + (sg*4 + 3)*PW + 3880)[o] = fmaxf(a3 + bb, 0.f);
  }
  __syncthreads();

  // ---- MLP2: 128 -> 64 (warp-per-sample, lane covers o and o+32) ----
  {
    float c0 = p.b2[lane], c1 = p.b2[lane + 32];
    #pragma unroll
    for (int k = 0; k < 128; k += 4) {
      float4 hv = *(const float4*)(mA + k);
      c0 += hv.x*p.w2[(k+0)*64+lane]    + hv.y*p.w2[(k+1)*64+lane]
          + hv.z*p.w2[(k+2)*64+lane]    + hv.w*p.w2[(k+3)*64+lane];
      c1 += hv.x*p.w2[(k+0)*64+lane+32] + hv.y*p.w2[(k+1)*64+lane+32]
          + hv.z*p.w2[(k+2)*64+lane+32] + hv.w*p.w2[(k+3)*64+lane+32];
    }
    mB[lane]      = fmaxf(c0, 0.f);
    mB[lane + 32] = fmaxf(c1, 0.f);
  }
  __syncwarp();

  // ---- MLP3: 64 -> 32 ----
  float d0 = p.b3[lane];
  #pragma unroll
  for (int k = 0; k < 64; k += 4) {
    float4 hv = *(const float4*)(mB + k);
    d0 += hv.x*p.w3[(k+0)*32+lane] + hv.y*p.w3[(k+1)*32+lane]
        + hv.z*p.w3[(k+2)*32+lane] + hv.w*p.w3[(k+3)*32+lane];
  }
  float h3v = fmaxf(d0, 0.f);

  // ---- MLP4: 32 -> 1, sigmoid ----
  float part = h3v * p.w4[lane];
  #pragma unroll
  for (int off = 16; off; off >>= 1) part += __shfl_xor_sync(0xffffffffu, part, off);
  if (lane == 0) {
    float z = part + p.b4[0];
    p.out[samp] = 1.0f / (1.0f + __expf(-z));
  }
}

extern "C" void kernel_launch(void* const* d_in, const int* in_sizes, int n_in,
                              void* d_out, int out_size)
{
  Params p;
  p.x   = (const int*)  d_in[0];
  p.emb = (const float*)d_in[1];
  p.wq0 = (const float*)d_in[2];  p.wk0 = (const float*)d_in[3];
  p.wv0 = (const float*)d_in[4];  p.wr0 = (const float*)d_in[5];
  p.wq1 = (const float*)d_in[6];  p.wk1 = (const float*)d_in[7];
  p.wv1 = (const float*)d_in[8];  p.wr1 = (const float*)d_in[9];
  p.wq2 = (const float*)d_in[10]; p.wk2 = (const float*)d_in[11];
  p.wv2 = (const float*)d_in[12]; p.wr2 = (const float*)d_in[13];
  p.w1  = (const float*)d_in[14]; p.b1  = (const float*)d_in[15];
  p.w2  = (const float*)d_in[16]; p.b2  = (const float*)d_in[17];
  p.w3  = (const float*)d_in[18]; p.b3  = (const float*)d_in[19];
  p.w4  = (const float*)d_in[20]; p.b4  = (const float*)d_in[21];
  p.out = (float*)d_out;

  const int smemBytes = (WBUF + WARPS * PW) * (int)sizeof(float);
  cudaFuncSetAttribute(autoint_kernel,
                       cudaFuncAttributeMaxDynamicSharedMemorySize, smemBytes);
  autoint_kernel<<<BATCH / WARPS, 256, smemBytes>>>(p);
}